// round 4
// baseline (speedup 1.0000x reference)
#include <cuda_runtime.h>
#include <math.h>

// BPR loss:
//   per_sample[b] = -( sum_{i<L, j<L, k<S} log_sigmoid( out[b,i,lab[b,j]] - out[b,i,neg[b,j,k]] ) ) / (L^2 * S)
//   result = sum_b per_sample[b]     (shape [1], float32)
//
// Inputs (metadata order; harness delivers int64 as int32):
//   d_in[0] output  : float32 [B, T, V]
//   d_in[1] labels  : int32   [B, T]
//   d_in[2] x_lens  : int32   [B]
//   d_in[3] uids    : int32   [B, 1]   (unused)
//   d_in[4] neg_ids : int32   [B, T, S]
//
// Strategy: per-sample column set is IDENTICAL across rows i. Prepass sorts the
// 2L column indices per b (bitonic-512) + rank permutation; main kernel gathers
// in ascending column order (DRAM row-buffer hits + intra-warp chunk coalescing)
// into smem, then computes pairs via the permutation.

#define SORT_N 512
#define MAXB   1024
#define ROWS_PER_BLOCK 4
#define SUBW 64

__device__ int            g_cols[MAXB][SORT_N];
__device__ unsigned short g_rank[MAXB][SORT_N];

__global__ void zero_out_kernel(float* __restrict__ out) {
    if (threadIdx.x == 0) out[0] = 0.0f;
}

__device__ __forceinline__ float warp_reduce_add(float v) {
#pragma unroll
    for (int off = 16; off > 0; off >>= 1)
        v += __shfl_down_sync(0xFFFFFFFFu, v, off);
    return v;
}

__device__ __forceinline__ float log_sigmoid_fast(float d) {
    return fminf(d, 0.0f) - __logf(1.0f + __expf(-fabsf(d)));
}

// ---------------- Prepass: sort column indices per sample ----------------
__global__ void __launch_bounds__(SORT_N)
sort_cols_kernel(const int* __restrict__ labels,   // [B,T]
                 const int* __restrict__ neg_ids,  // [B,T] (S==1)
                 const int* __restrict__ x_lens,   // [B]
                 int T)
{
    const int b = blockIdx.x;
    const int L = x_lens[b];
    const int n = 2 * L;
    const int t = threadIdx.x;

    __shared__ int s_key[SORT_N];
    __shared__ unsigned short s_idx[SORT_N];

    int k;
    if (t < L)          k = labels[b * T + t];
    else if (t < n)     k = neg_ids[b * T + (t - L)];
    else                k = 0x7FFFFFFF;          // sentinel -> sorts to end
    s_key[t] = k;
    s_idx[t] = (unsigned short)t;

    // bitonic sort (ascending), SORT_N power of 2
    for (int size = 2; size <= SORT_N; size <<= 1) {
        for (int stride = size >> 1; stride > 0; stride >>= 1) {
            __syncthreads();
            const int p = t ^ stride;
            if (p > t) {
                const bool asc = ((t & size) == 0);
                const int ka = s_key[t], kb = s_key[p];
                if ((ka > kb) == asc) {
                    s_key[t] = kb; s_key[p] = ka;
                    const unsigned short ia = s_idx[t];
                    s_idx[t] = s_idx[p]; s_idx[p] = ia;
                }
            }
        }
    }
    __syncthreads();

    g_cols[b][t] = s_key[t];
    const int orig = s_idx[t];
    if (orig < n) g_rank[b][orig] = (unsigned short)t;
}

// ---------------- Main kernel: sorted gather + pair compute ----------------
__global__ void __launch_bounds__(256)
bpr_loss_sorted_kernel(const float* __restrict__ out3d,  // [B,T,V]
                       const int* __restrict__ x_lens,   // [B]
                       float* __restrict__ result,       // [1]
                       int T, int V)
{
    const int b = blockIdx.y;
    const int L = x_lens[b];
    const int i0 = blockIdx.x * ROWS_PER_BLOCK;
    if (i0 >= L) return;

    const int sub = threadIdx.x & (SUBW - 1);
    const int ri  = threadIdx.x / SUBW;
    const int i   = i0 + ri;
    const int n   = 2 * L;

    __shared__ float vals[ROWS_PER_BLOCK][SORT_N];

    if (i < L) {
        const float* __restrict__ row = out3d + ((size_t)b * T + i) * (size_t)V;
        const int* __restrict__ cols = g_cols[b];
#pragma unroll 4
        for (int s = sub; s < n; s += SUBW)
            vals[ri][s] = __ldg(row + __ldg(cols + s));
    }
    __syncthreads();

    float acc = 0.0f;
    if (i < L) {
        const unsigned short* __restrict__ rk = g_rank[b];
        for (int j = sub; j < L; j += SUBW) {
            const float pv = vals[ri][rk[j]];
            const float nv = vals[ri][rk[L + j]];
            acc += log_sigmoid_fast(pv - nv);
        }
    }

    __shared__ float warp_sums[8];
    const int lane = threadIdx.x & 31;
    const int wid  = threadIdx.x >> 5;
    acc = warp_reduce_add(acc);
    if (lane == 0) warp_sums[wid] = acc;
    __syncthreads();
    if (wid == 0) {
        float v = (lane < 8) ? warp_sums[lane] : 0.0f;
        v = warp_reduce_add(v);
        if (lane == 0) {
            const float Lf = (float)L;
            atomicAdd(result, v * (-1.0f / (Lf * Lf)));
        }
    }
}

// ---------------- Fallback (general S / large T / large B) ----------------
__global__ void __launch_bounds__(256)
bpr_loss_fallback_kernel(const float* __restrict__ out3d,
                         const int* __restrict__ labels,
                         const int* __restrict__ x_lens,
                         const int* __restrict__ neg_ids,
                         float* __restrict__ result,
                         int T, int V, int S)
{
    const int b = blockIdx.y;
    const int i = blockIdx.x;
    const int L = x_lens[b];
    if (i >= L) return;

    const float* __restrict__ row = out3d + ((size_t)b * T + i) * (size_t)V;
    const int* __restrict__ lab = labels + (size_t)b * T;
    const int* __restrict__ neg = neg_ids + (size_t)b * T * S;

    float acc = 0.0f;
    for (int j = threadIdx.x; j < L; j += blockDim.x) {
        const float pv = __ldg(row + lab[j]);
        for (int k = 0; k < S; ++k)
            acc += log_sigmoid_fast(pv - __ldg(row + neg[(size_t)j * S + k]));
    }

    __shared__ float warp_sums[8];
    const int lane = threadIdx.x & 31;
    const int wid  = threadIdx.x >> 5;
    acc = warp_reduce_add(acc);
    if (lane == 0) warp_sums[wid] = acc;
    __syncthreads();
    if (wid == 0) {
        float v = (lane < 8) ? warp_sums[lane] : 0.0f;
        v = warp_reduce_add(v);
        if (lane == 0) {
            const float Lf = (float)L;
            atomicAdd(result, v * (-1.0f / (Lf * Lf * (float)S)));
        }
    }
}

extern "C" void kernel_launch(void* const* d_in, const int* in_sizes, int n_in,
                              void* d_out, int out_size)
{
    const float* out3d   = (const float*)d_in[0];
    const int*   labels  = (const int*)d_in[1];
    const int*   x_lens  = (const int*)d_in[2];
    const int*   neg_ids = (const int*)d_in[4];
    float* result = (float*)d_out;

    const int B = in_sizes[2];
    const int T = in_sizes[1] / B;
    const int V = in_sizes[0] / (B * T);
    const int S = in_sizes[4] / (B * T);

    zero_out_kernel<<<1, 32>>>(result);

    if (S == 1 && 2 * T <= SORT_N && B <= MAXB) {
        sort_cols_kernel<<<B, SORT_N>>>(labels, neg_ids, x_lens, T);
        dim3 grid((T + ROWS_PER_BLOCK - 1) / ROWS_PER_BLOCK, B);
        bpr_loss_sorted_kernel<<<grid, 256>>>(out3d, x_lens, result, T, V);
    } else {
        dim3 grid(T, B);
        bpr_loss_fallback_kernel<<<grid, 256>>>(out3d, labels, x_lens, neg_ids,
                                                result, T, V, S);
    }
}

// round 5
// speedup vs baseline: 1.0572x; 1.0572x over previous
#include <cuda_runtime.h>
#include <math.h>

// BPR loss:
//   per_sample[b] = -( sum_{i<L, j<L, k<S} log_sigmoid( out[b,i,lab[b,j]] - out[b,i,neg[b,j,k]] ) ) / (L^2 * S)
//   result = sum_b per_sample[b]     (shape [1], float32)
//
// Inputs (harness delivers int64 as int32):
//   d_in[0] output  : float32 [B, T, V]
//   d_in[1] labels  : int32   [B, T]
//   d_in[2] x_lens  : int32   [B]
//   d_in[3] uids    : int32   [B, 1]  (unused)
//   d_in[4] neg_ids : int32   [B, T, S]
//
// Sorted-gather strategy: per-sample column set is identical across rows i.
// Prepass sorts packed (col<<9 | orig) keys per sample; main kernel sweeps the
// row in ascending column order (DRAM row-buffer locality) and SCATTERS each
// value straight into pos[orig]/neg[orig-L] in smem; the compute loop is then
// a sequential, conflict-free pass over (pos[j], neg[j]).

#define SORT_N 512
#define MAXB   1024
#define ROWS_PER_BLOCK 4
#define SUBW 64
#define MAXT 256   // this path requires T <= MAXT (2T <= SORT_N)

__device__ int g_sorted[MAXB][SORT_N];   // packed (col << 9) | orig

__global__ void zero_out_kernel(float* __restrict__ out) {
    if (threadIdx.x == 0) out[0] = 0.0f;
}

__device__ __forceinline__ float warp_reduce_add(float v) {
#pragma unroll
    for (int off = 16; off > 0; off >>= 1)
        v += __shfl_down_sync(0xFFFFFFFFu, v, off);
    return v;
}

__device__ __forceinline__ float log_sigmoid_fast(float d) {
    return fminf(d, 0.0f) - __logf(1.0f + __expf(-fabsf(d)));
}

// ---------------- Prepass: sort packed column keys per sample ----------------
__global__ void __launch_bounds__(SORT_N)
sort_cols_kernel(const int* __restrict__ labels,   // [B,T]
                 const int* __restrict__ neg_ids,  // [B,T] (S==1)
                 const int* __restrict__ x_lens,   // [B]
                 int T)
{
    const int b = blockIdx.x;
    const int L = x_lens[b];
    const int n = 2 * L;
    const int t = threadIdx.x;

    __shared__ int s_key[SORT_N];

    int k;
    if (t < L)      k = (labels[b * T + t] << 9) | t;
    else if (t < n) k = (neg_ids[b * T + (t - L)] << 9) | t;
    else            k = 0x7FFFFFFF;   // sentinel -> end
    s_key[t] = k;

    for (int size = 2; size <= SORT_N; size <<= 1) {
        for (int stride = size >> 1; stride > 0; stride >>= 1) {
            __syncthreads();
            const int p = t ^ stride;
            if (p > t) {
                const bool asc = ((t & size) == 0);
                const int ka = s_key[t], kb = s_key[p];
                if ((ka > kb) == asc) { s_key[t] = kb; s_key[p] = ka; }
            }
        }
    }
    __syncthreads();
    g_sorted[b][t] = s_key[t];
}

// ---------------- Main: sorted gather with scatter-to-smem ----------------
__global__ void __launch_bounds__(256)
bpr_loss_sorted_kernel(const float* __restrict__ out3d,  // [B,T,V]
                       const int* __restrict__ x_lens,   // [B]
                       float* __restrict__ result,       // [1]
                       int T, int V)
{
    const int b = blockIdx.y;
    const int L = x_lens[b];
    const int i0 = blockIdx.x * ROWS_PER_BLOCK;
    if (i0 >= L) return;

    const int sub = threadIdx.x & (SUBW - 1);
    const int ri  = threadIdx.x / SUBW;
    const int i   = i0 + ri;
    const int n   = 2 * L;

    __shared__ float pos_v[ROWS_PER_BLOCK][MAXT];
    __shared__ float neg_v[ROWS_PER_BLOCK][MAXT];

    if (i < L) {
        const float* __restrict__ row = out3d + ((size_t)b * T + i) * (size_t)V;
        const int* __restrict__ srt = g_sorted[b];
        // ascending-column sweep; scatter by original index
#pragma unroll 2
        for (int s = sub; s < n; s += SUBW) {
            const int packed = __ldg(srt + s);
            const int col  = packed >> 9;
            const int orig = packed & 511;
            const float v = __ldg(row + col);
            if (orig < L) pos_v[ri][orig] = v;
            else          neg_v[ri][orig - L] = v;
        }
    }
    __syncthreads();

    float acc = 0.0f;
    if (i < L) {
        // sequential, conflict-free pairing
        for (int j = sub; j < L; j += SUBW)
            acc += log_sigmoid_fast(pos_v[ri][j] - neg_v[ri][j]);
    }

    __shared__ float warp_sums[8];
    const int lane = threadIdx.x & 31;
    const int wid  = threadIdx.x >> 5;
    acc = warp_reduce_add(acc);
    if (lane == 0) warp_sums[wid] = acc;
    __syncthreads();
    if (wid == 0) {
        float v = (lane < 8) ? warp_sums[lane] : 0.0f;
        v = warp_reduce_add(v);
        if (lane == 0) {
            const float Lf = (float)L;
            atomicAdd(result, v * (-1.0f / (Lf * Lf)));
        }
    }
}

// ---------------- Fallback (general S / large T / large B) ----------------
__global__ void __launch_bounds__(256)
bpr_loss_fallback_kernel(const float* __restrict__ out3d,
                         const int* __restrict__ labels,
                         const int* __restrict__ x_lens,
                         const int* __restrict__ neg_ids,
                         float* __restrict__ result,
                         int T, int V, int S)
{
    const int b = blockIdx.y;
    const int i = blockIdx.x;
    const int L = x_lens[b];
    if (i >= L) return;

    const float* __restrict__ row = out3d + ((size_t)b * T + i) * (size_t)V;
    const int* __restrict__ lab = labels + (size_t)b * T;
    const int* __restrict__ neg = neg_ids + (size_t)b * T * S;

    float acc = 0.0f;
    for (int j = threadIdx.x; j < L; j += blockDim.x) {
        const float pv = __ldg(row + lab[j]);
        for (int k = 0; k < S; ++k)
            acc += log_sigmoid_fast(pv - __ldg(row + neg[(size_t)j * S + k]));
    }

    __shared__ float warp_sums[8];
    const int lane = threadIdx.x & 31;
    const int wid  = threadIdx.x >> 5;
    acc = warp_reduce_add(acc);
    if (lane == 0) warp_sums[wid] = acc;
    __syncthreads();
    if (wid == 0) {
        float v = (lane < 8) ? warp_sums[lane] : 0.0f;
        v = warp_reduce_add(v);
        if (lane == 0) {
            const float Lf = (float)L;
            atomicAdd(result, v * (-1.0f / (Lf * Lf * (float)S)));
        }
    }
}

extern "C" void kernel_launch(void* const* d_in, const int* in_sizes, int n_in,
                              void* d_out, int out_size)
{
    const float* out3d   = (const float*)d_in[0];
    const int*   labels  = (const int*)d_in[1];
    const int*   x_lens  = (const int*)d_in[2];
    const int*   neg_ids = (const int*)d_in[4];
    float* result = (float*)d_out;

    const int B = in_sizes[2];
    const int T = in_sizes[1] / B;
    const int V = in_sizes[0] / (B * T);
    const int S = in_sizes[4] / (B * T);

    zero_out_kernel<<<1, 32>>>(result);

    if (S == 1 && T <= MAXT && B <= MAXB) {
        sort_cols_kernel<<<B, SORT_N>>>(labels, neg_ids, x_lens, T);
        dim3 grid((T + ROWS_PER_BLOCK - 1) / ROWS_PER_BLOCK, B);
        bpr_loss_sorted_kernel<<<grid, 256>>>(out3d, x_lens, result, T, V);
    } else {
        dim3 grid(T, B);
        bpr_loss_fallback_kernel<<<grid, 256>>>(out3d, labels, x_lens, neg_ids,
                                                result, T, V, S);
    }
}

// round 6
// speedup vs baseline: 1.2615x; 1.1933x over previous
#include <cuda_runtime.h>
#include <math.h>

// BPR loss:
//   per_sample[b] = -( sum_{i<L, j<L, k<S} log_sigmoid( out[b,i,lab[b,j]] - out[b,i,neg[b,j,k]] ) ) / (L^2 * S)
//   result = sum_b per_sample[b]     (shape [1], float32)
//
// Inputs (harness delivers int64 as int32):
//   d_in[0] output  : float32 [B, T, V]
//   d_in[1] labels  : int32   [B, T]
//   d_in[2] x_lens  : int32   [B]
//   d_in[3] uids    : int32   [B, 1]  (unused)
//   d_in[4] neg_ids : int32   [B, T, S]
//
// R6: R2 structure (best: 33.0us main). Experiment: row gathers via __ldcg
// (L2-only, no L1 line allocation) to test whether the L1-allocating path
// inflates DRAM fetch granularity on the random 4B gathers.

__global__ void zero_out_kernel(float* __restrict__ out) {
    if (threadIdx.x == 0) out[0] = 0.0f;
}

__device__ __forceinline__ float warp_reduce_add(float v) {
#pragma unroll
    for (int off = 16; off > 0; off >>= 1)
        v += __shfl_down_sync(0xFFFFFFFFu, v, off);
    return v;
}

__device__ __forceinline__ float log_sigmoid_fast(float d) {
    // min(d,0) - log(1 + exp(-|d|)); exp arg <= 0 so log arg in (1,2]
    return fminf(d, 0.0f) - __logf(1.0f + __expf(-fabsf(d)));
}

__global__ void __launch_bounds__(256)
bpr_loss_kernel(const float* __restrict__ out3d,   // [B,T,V]
                const int* __restrict__ labels,    // [B,T]
                const int* __restrict__ x_lens,    // [B]
                const int* __restrict__ neg_ids,   // [B,T,S]
                float* __restrict__ result,        // [1]
                int T, int V, int S)
{
    const int b = blockIdx.y;
    const int i = blockIdx.x;
    const int L = x_lens[b];
    if (i >= L) return;

    const float* __restrict__ row = out3d + ((size_t)b * T + i) * (size_t)V;
    const int* __restrict__ lab = labels + (size_t)b * T;
    const int* __restrict__ neg = neg_ids + (size_t)b * T * S;

    float acc = 0.0f;
    if (S == 1) {
        for (int j = threadIdx.x; j < L; j += blockDim.x) {
            const int c_pos = __ldg(lab + j);
            const int c_neg = __ldg(neg + j);
            // L2-only gathers: no L1 line allocation (zero reuse anyway)
            const float pv = __ldcg(row + c_pos);
            const float nv = __ldcg(row + c_neg);
            acc += log_sigmoid_fast(pv - nv);
        }
    } else {
        for (int j = threadIdx.x; j < L; j += blockDim.x) {
            const int c_pos = __ldg(lab + j);
            const float pv = __ldcg(row + c_pos);
            for (int k = 0; k < S; ++k) {
                const int c_neg = __ldg(neg + (size_t)j * S + k);
                acc += log_sigmoid_fast(pv - __ldcg(row + c_neg));
            }
        }
    }

    // block reduction
    __shared__ float warp_sums[8];
    const int lane = threadIdx.x & 31;
    const int wid  = threadIdx.x >> 5;
    acc = warp_reduce_add(acc);
    if (lane == 0) warp_sums[wid] = acc;
    __syncthreads();
    if (wid == 0) {
        float v = (lane < 8) ? warp_sums[lane] : 0.0f;
        v = warp_reduce_add(v);
        if (lane == 0) {
            const float Lf = (float)L;
            atomicAdd(result, v * (-1.0f / (Lf * Lf * (float)S)));
        }
    }
}

extern "C" void kernel_launch(void* const* d_in, const int* in_sizes, int n_in,
                              void* d_out, int out_size)
{
    const float* out3d   = (const float*)d_in[0];
    const int*   labels  = (const int*)d_in[1];
    const int*   x_lens  = (const int*)d_in[2];
    const int*   neg_ids = (const int*)d_in[4];
    float* result = (float*)d_out;

    const int B = in_sizes[2];                 // x_lens: B
    const int T = in_sizes[1] / B;             // labels: B*T
    const int V = in_sizes[0] / (B * T);       // output: B*T*V
    const int S = in_sizes[4] / (B * T);       // neg_ids: B*T*S

    zero_out_kernel<<<1, 32>>>(result);

    dim3 grid(T, B);
    bpr_loss_kernel<<<grid, 256>>>(out3d, labels, x_lens, neg_ids, result, T, V, S);
}